// round 10
// baseline (speedup 1.0000x reference)
#include <cuda_runtime.h>
#include <cuda_bf16.h>
#include <cstdint>

#define BATCH 64
#define LQS   1024
#define LKS   1024
#define DIMS  64
#define NTHREADS 128
#define LQT   64        /* q-rows per CTA */
#define BKT   32        /* keys per tile */
#define NTILE (LKS / BKT)

/* ---- shared memory byte offsets ---- */
#define OFF_SL   0                       /* 64 floats: per-row inv */
#define OFF_QHI  1024                    /* 64 x 128B = 8KB */
#define OFF_QLO  (OFF_QHI + 8192)
#define OFF_CONV (OFF_QLO + 8192)        /* 17408; two conv buffers of 16KB */
#define OFFC_KHI 0
#define OFFC_KLO 4096
#define OFFC_VHI 8192
#define OFFC_VLO 12288
#define CONV_BYTES 16384
#define OFF_GM   (OFF_CONV + 2 * CONV_BYTES)  /* 50176; 2 x (64 rows x 144B) */
#define GM_STRIDE_B 144
#define GM_STRIDE_I 36
#define GM_BYTES (LQT * GM_STRIDE_B)          /* 9216 */
#define SMEM_BYTES (OFF_GM + 2 * GM_BYTES)    /* 68608 */

#define SWZ(x) ((x) ^ (((x) >> 3) & 0x70))

/* ------------------------- helpers ------------------------- */
__device__ __forceinline__ uint32_t smem_u32(const void* p) {
    uint32_t a;
    asm("{ .reg .u64 t; cvta.to.shared.u64 t, %1; cvt.u32.u64 %0, t; }" : "=r"(a) : "l"(p));
    return a;
}
__device__ __forceinline__ void cp16(uint32_t d, const void* s) {
    asm volatile("cp.async.cg.shared.global [%0], [%1], 16;" :: "r"(d), "l"(s) : "memory");
}
#define CP_COMMIT() asm volatile("cp.async.commit_group;" ::: "memory")
__device__ __forceinline__ void ldm_x4(uint32_t* d, uint32_t a) {
    asm volatile("ldmatrix.sync.aligned.m8n8.x4.shared.b16 {%0,%1,%2,%3}, [%4];"
        : "=r"(d[0]), "=r"(d[1]), "=r"(d[2]), "=r"(d[3]) : "r"(a));
}
__device__ __forceinline__ void ldm_x4t(uint32_t* d, uint32_t a) {
    asm volatile("ldmatrix.sync.aligned.m8n8.x4.trans.shared.b16 {%0,%1,%2,%3}, [%4];"
        : "=r"(d[0]), "=r"(d[1]), "=r"(d[2]), "=r"(d[3]) : "r"(a));
}
__device__ __forceinline__ void mma16816(float* c, const uint32_t* a, const uint32_t* b) {
    asm volatile("mma.sync.aligned.m16n8k16.row.col.f32.bf16.bf16.f32 "
        "{%0,%1,%2,%3}, {%4,%5,%6,%7}, {%8,%9}, {%0,%1,%2,%3};"
        : "+f"(c[0]), "+f"(c[1]), "+f"(c[2]), "+f"(c[3])
        : "r"(a[0]), "r"(a[1]), "r"(a[2]), "r"(a[3]), "r"(b[0]), "r"(b[1]));
}
__device__ __forceinline__ uint32_t pack2bf(float a, float b) {
    __nv_bfloat16 ha = __float2bfloat16(a), hb = __float2bfloat16(b);
    return (uint32_t)__bfloat16_as_ushort(ha) | ((uint32_t)__bfloat16_as_ushort(hb) << 16);
}
__device__ __forceinline__ void split2(float2 v, uint32_t& hw, uint32_t& lw) {
    __nv_bfloat16 h0 = __float2bfloat16(v.x), h1 = __float2bfloat16(v.y);
    hw = (uint32_t)__bfloat16_as_ushort(h0) | ((uint32_t)__bfloat16_as_ushort(h1) << 16);
    lw = pack2bf(v.x - __bfloat162float(h0), v.y - __bfloat162float(h1));
}

/* load a 32-key K/V tile into registers (4 float4 each, 128 threads) */
__device__ __forceinline__ void ldg_kv(const float4* Ks, const float4* Vs, int tid,
                                       float4* kr, float4* vr) {
    #pragma unroll
    for (int i = 0; i < 4; ++i) { kr[i] = Ks[tid + NTHREADS * i]; vr[i] = Vs[tid + NTHREADS * i]; }
}
/* split + store K/V registers into a conv buffer */
__device__ __forceinline__ void sts_kv(char* smem, uint32_t cb, int tid,
                                       const float4* kr, const float4* vr) {
    #pragma unroll
    for (int i = 0; i < 4; ++i) {
        int idx = tid + NTHREADS * i;
        int row = idx >> 4, dp4 = idx & 15;
        uint32_t off = SWZ((uint32_t)(row * 128 + dp4 * 8));
        uint32_t h0, l0, h1, l1;
        split2(make_float2(kr[i].x, kr[i].y), h0, l0);
        split2(make_float2(kr[i].z, kr[i].w), h1, l1);
        *(uint2*)(smem + cb + OFFC_KHI + off) = make_uint2(h0, h1);
        *(uint2*)(smem + cb + OFFC_KLO + off) = make_uint2(l0, l1);
        split2(make_float2(vr[i].x, vr[i].y), h0, l0);
        split2(make_float2(vr[i].z, vr[i].w), h1, l1);
        *(uint2*)(smem + cb + OFFC_VHI + off) = make_uint2(h0, h1);
        *(uint2*)(smem + cb + OFFC_VLO + off) = make_uint2(l0, l1);
    }
}

/* ============================ main kernel ============================ */
__global__ __launch_bounds__(NTHREADS, 2)
void attn_mma_kernel(const float* __restrict__ Qg, const float* __restrict__ Kg,
                     const float* __restrict__ Vg,
                     const int* __restrict__ qmask, const int* __restrict__ kmask,
                     const int* __restrict__ gmask,
                     float* __restrict__ out_av, float* __restrict__ out_attn)
{
    extern __shared__ char smem[];
    const uint32_t sb = smem_u32(smem);
    float* sL = (float*)(smem + OFF_SL);

    const int tid  = threadIdx.x;
    const int warp = tid >> 5;
    const int lane = tid & 31;
    const int l16  = lane & 15;
    const int qg   = lane & 3;
    const int r    = lane >> 2;
    const int b    = blockIdx.y;
    const int q0   = blockIdx.x * LQT;

    const int* kmb = kmask + (size_t)b * LKS;
    const int* gm0 = gmask + ((size_t)(b * LQS + q0)) * LKS;
    const float4* Kbase = (const float4*)(Kg + ((size_t)(b * LKS)) * DIMS);
    const float4* Vbase = (const float4*)(Vg + ((size_t)(b * LKS)) * DIMS);

    /* ---- group0: gmask tile0 (64 rows x 32 ints) ---- */
    {
        for (int i = tid; i < 512; i += NTHREADS) {
            int row = i >> 3, c = i & 7;
            cp16(sb + OFF_GM + row * GM_STRIDE_B + c * 16, gm0 + (size_t)row * LKS + c * 4);
        }
        CP_COMMIT();
    }

    /* ---- LDG K/V tile 0 into registers ---- */
    float4 kr[4], vr[4];
    ldg_kv(Kbase, Vbase, tid, kr, vr);

    /* ---- stage Q (scaled 1/8), split hi/lo, SW128 ---- */
    {
        const float4* Qg4 = (const float4*)(Qg + ((size_t)(b * LQS + q0)) * DIMS);
        #pragma unroll
        for (int i = 0; i < 8; ++i) {
            int idx = tid + NTHREADS * i;
            int row = idx >> 4, dp4 = idx & 15;
            float4 v = Qg4[idx];
            v.x *= 0.125f; v.y *= 0.125f; v.z *= 0.125f; v.w *= 0.125f;
            uint32_t h0, l0, h1, l1;
            split2(make_float2(v.x, v.y), h0, l0);
            split2(make_float2(v.z, v.w), h1, l1);
            uint32_t off = SWZ((uint32_t)(row * 128 + dp4 * 8));
            *(uint2*)(smem + OFF_QHI + off) = make_uint2(h0, h1);
            *(uint2*)(smem + OFF_QLO + off) = make_uint2(l0, l1);
        }
    }
    __syncthreads();

    /* ---- per-warp Q A-fragments (16 rows per warp) ---- */
    uint32_t qh[4][4], ql[4][4];
    {
        const int qrow = warp * 16 + l16;
        const int cgrp = (lane >> 4) * 16;
        #pragma unroll
        for (int t = 0; t < 4; ++t) {
            uint32_t off = SWZ((uint32_t)(qrow * 128 + t * 32 + cgrp));
            ldm_x4(qh[t], sb + OFF_QHI + off);
            ldm_x4(ql[t], sb + OFF_QLO + off);
        }
    }

    /* ---- convert tile 0 into conv buf 0 ---- */
    sts_kv(smem, OFF_CONV, tid, kr, vr);
    __syncthreads();

    float oc[8][4];
    #pragma unroll
    for (int j = 0; j < 8; ++j)
        #pragma unroll
        for (int c = 0; c < 4; ++c) oc[j][c] = 0.f;
    float l0s = 0.f, l1s = 0.f;

    const int row_r  = warp * 16 + r;
    const int row_r8 = row_r + 8;
    const size_t gq_r  = (size_t)(b * LQS + q0 + row_r);
    const size_t gq_r8 = gq_r + 8;
    float* attn_r  = out_attn + gq_r  * LKS;
    float* attn_r8 = out_attn + gq_r8 * LKS;

    #pragma unroll 1
    for (int kt = 0; kt < NTILE; ++kt) {
        const int kbase = kt * BKT;
        const uint32_t cb  = OFF_CONV + (uint32_t)((kt & 1) * CONV_BYTES);
        const uint32_t cbn = OFF_CONV + (uint32_t)(((kt + 1) & 1) * CONV_BYTES);

        /* [A] LDG next K/V + cp.async next gmask */
        if (kt + 1 < NTILE) {
            const int nb = kbase + BKT;
            ldg_kv(Kbase + nb * (DIMS / 4), Vbase + nb * (DIMS / 4), tid, kr, vr);
            const uint32_t gbuf = sb + OFF_GM + (uint32_t)(((kt + 1) & 1) * GM_BYTES);
            const int* Gs = gm0 + nb;
            for (int i = tid; i < 512; i += NTHREADS) {
                int row = i >> 3, c = i & 7;
                cp16(gbuf + row * GM_STRIDE_B + c * 16, Gs + (size_t)row * LKS + c * 4);
            }
            CP_COMMIT();
        }

        /* [B] S = Q K^T with bf16 EC (hi*hi + lo*hi + hi*lo), 32 keys */
        float sc[4][4];
        #pragma unroll
        for (int j = 0; j < 4; ++j)
            #pragma unroll
            for (int c = 0; c < 4; ++c) sc[j][c] = 0.f;

        #pragma unroll
        for (int t = 0; t < 4; ++t) {
            #pragma unroll
            for (int jp = 0; jp < 2; ++jp) {
                uint32_t kh4[4], kl4[4];
                int krow = jp * 16 + (lane & 7) + ((lane >> 4) << 3);
                uint32_t off = SWZ((uint32_t)(krow * 128 + t * 32 + ((lane >> 3) & 1) * 16));
                ldm_x4(kh4, sb + cb + OFFC_KHI + off);
                ldm_x4(kl4, sb + cb + OFFC_KLO + off);
                mma16816(sc[2*jp],   qh[t], kh4);
                mma16816(sc[2*jp],   ql[t], kh4);
                mma16816(sc[2*jp],   qh[t], kl4);
                mma16816(sc[2*jp+1], qh[t], kh4 + 2);
                mma16816(sc[2*jp+1], ql[t], kh4 + 2);
                mma16816(sc[2*jp+1], qh[t], kl4 + 2);
            }
        }

        /* [C] gmask(kt) landed (group order) + buffer handoff */
        if (kt + 1 < NTILE) asm volatile("cp.async.wait_group 1;" ::: "memory");
        else                asm volatile("cp.async.wait_group 0;" ::: "memory");
        __syncthreads();

        /* [D] convert next tile into the other conv buffer */
        if (kt + 1 < NTILE) sts_kv(smem, cbn, tid, kr, vr);

        /* [E]+[F] per 16-key group: epilogue then PV MMAs */
        const int* smG = (const int*)(smem + OFF_GM + (size_t)((kt & 1) * GM_BYTES));
        #pragma unroll
        for (int t2 = 0; t2 < 2; ++t2) {
            uint32_t pa_h[4], pa_l[4];
            #pragma unroll
            for (int u = 0; u < 2; ++u) {
                const int j = 2 * t2 + u;
                const int c64 = j * 8 + 2 * qg;
                int2 km = __ldg((const int2*)(kmb + kbase + c64));
                int2 g0 = *(const int2*)(smG + row_r  * GM_STRIDE_I + c64);
                int2 g1 = *(const int2*)(smG + row_r8 * GM_STRIDE_I + c64);
                float e0 = (km.x && g0.x) ? __expf(sc[j][0]) : 0.f;
                float e1 = (km.y && g0.y) ? __expf(sc[j][1]) : 0.f;
                float e2 = (km.x && g1.x) ? __expf(sc[j][2]) : 0.f;
                float e3 = (km.y && g1.y) ? __expf(sc[j][3]) : 0.f;
                l0s += e0 + e1; l1s += e2 + e3;
                *(float2*)(attn_r  + kbase + c64) = make_float2(e0, e1);
                *(float2*)(attn_r8 + kbase + c64) = make_float2(e2, e3);
                uint32_t hw, lw;
                split2(make_float2(e0, e1), hw, lw); pa_h[2*u]   = hw; pa_l[2*u]   = lw;
                split2(make_float2(e2, e3), hw, lw); pa_h[2*u+1] = hw; pa_l[2*u+1] = lw;
            }
            #pragma unroll
            for (int j2p = 0; j2p < 4; ++j2p) {
                uint32_t vh4[4], vl4[4];
                int vrow = t2 * 16 + (lane & 15);
                uint32_t off = SWZ((uint32_t)(vrow * 128 + j2p * 32 + (lane >> 4) * 16));
                ldm_x4t(vh4, sb + cb + OFFC_VHI + off);
                ldm_x4t(vl4, sb + cb + OFFC_VLO + off);
                mma16816(oc[2*j2p],   pa_h, vh4);
                mma16816(oc[2*j2p],   pa_h, vl4);
                mma16816(oc[2*j2p],   pa_l, vh4);
                mma16816(oc[2*j2p+1], pa_h, vh4 + 2);
                mma16816(oc[2*j2p+1], pa_h, vl4 + 2);
                mma16816(oc[2*j2p+1], pa_l, vh4 + 2);
            }
        }
        __syncthreads();
    }

    /* ---- row sums across quad lanes, inv, store attn_value ---- */
    l0s += __shfl_xor_sync(0xffffffffu, l0s, 1);
    l0s += __shfl_xor_sync(0xffffffffu, l0s, 2);
    l1s += __shfl_xor_sync(0xffffffffu, l1s, 1);
    l1s += __shfl_xor_sync(0xffffffffu, l1s, 2);
    const float inv0 = (qmask[gq_r]  != 0) ? (1.0f / l0s) : 0.0f;
    const float inv1 = (qmask[gq_r8] != 0) ? (1.0f / l1s) : 0.0f;
    if (qg == 0) { sL[row_r] = inv0; sL[row_r8] = inv1; }

    {
        float* av_r  = out_av + gq_r  * DIMS;
        float* av_r8 = out_av + gq_r8 * DIMS;
        #pragma unroll
        for (int j2 = 0; j2 < 8; ++j2) {
            const int col = j2 * 8 + 2 * qg;
            *(float2*)(av_r  + col) = make_float2(oc[j2][0] * inv0, oc[j2][1] * inv0);
            *(float2*)(av_r8 + col) = make_float2(oc[j2][2] * inv1, oc[j2][3] * inv1);
        }
    }

    /* ---- fused normalize of this CTA's attn rows (L2-resident) ---- */
    __threadfence_block();
    __syncthreads();
    {
        float4* base = (float4*)(out_attn + ((size_t)(b * LQS + q0)) * LKS);
        for (int i = tid; i < LQT * 256; i += NTHREADS) {
            const float inv = sL[i >> 8];
            float4 v = base[i];
            v.x *= inv; v.y *= inv; v.z *= inv; v.w *= inv;
            base[i] = v;
        }
    }
}

extern "C" void kernel_launch(void* const* d_in, const int* in_sizes, int n_in,
                              void* d_out, int out_size) {
    const float* Q  = (const float*)d_in[0];
    const float* K  = (const float*)d_in[1];
    const float* V  = (const float*)d_in[2];
    const int*   qm = (const int*)d_in[3];
    const int*   km = (const int*)d_in[4];
    const int*   mk = (const int*)d_in[5];

    const long long NAV = (long long)BATCH * LQS * DIMS;
    float* out  = (float*)d_out;
    float* av   = out;
    float* attn = out + NAV;
    (void)out_size; (void)in_sizes; (void)n_in;

    cudaFuncSetAttribute(attn_mma_kernel, cudaFuncAttributeMaxDynamicSharedMemorySize,
                         SMEM_BYTES);
    dim3 grid(LQS / LQT, BATCH);
    attn_mma_kernel<<<grid, NTHREADS, SMEM_BYTES>>>(Q, K, V, qm, km, mk, av, attn);
}

// round 11
// speedup vs baseline: 1.0729x; 1.0729x over previous
#include <cuda_runtime.h>
#include <cuda_bf16.h>
#include <cstdint>

#define BATCH 64
#define LQS   1024
#define LKS   1024
#define DIMS  64
#define NTHREADS 256
#define LQT   64        /* q-rows per CTA (4 pairs x 16) */
#define BKT   64        /* keys per tile */
#define NTILE 16

/* ---- shared memory byte offsets ---- */
#define OFF_SLH  0                      /* 2 x 64 floats: half row sums */
#define OFF_SINV 512                    /* 64 floats: inv */
#define OFF_Q    1024                   /* Qhi 8K */
#define OFF_QLO  (OFF_Q + 8192)         /* Qlo 8K */
#define OFF_KV   17408                  /* ring: 2 x 32K (Khi,Klo,Vhi,Vlo 8K each) */
#define KV_BYTES 32768
#define OFF_P    (OFF_KV + 2 * KV_BYTES)    /* 82944: 4 pairs x (hi 2K + lo 2K) */
#define SMEM_BYTES (OFF_P + 16384)          /* 99328 */

#define SWZ(x) ((x) ^ (((x) >> 3) & 0x70))

/* ---- global scratch: pre-swizzled bf16 hi/lo K and V tiles (8KB per tile) ---- */
__device__ uint4 g_Khi[BATCH * NTILE * 512];
__device__ uint4 g_Klo[BATCH * NTILE * 512];
__device__ uint4 g_Vhi[BATCH * NTILE * 512];
__device__ uint4 g_Vlo[BATCH * NTILE * 512];

/* ------------------------- helpers ------------------------- */
__device__ __forceinline__ uint32_t smem_u32(const void* p) {
    uint32_t a;
    asm("{ .reg .u64 t; cvta.to.shared.u64 t, %1; cvt.u32.u64 %0, t; }" : "=r"(a) : "l"(p));
    return a;
}
__device__ __forceinline__ void cp16(uint32_t d, const void* s) {
    asm volatile("cp.async.cg.shared.global [%0], [%1], 16;" :: "r"(d), "l"(s) : "memory");
}
#define CP_COMMIT() asm volatile("cp.async.commit_group;" ::: "memory")
__device__ __forceinline__ void ldm_x4(uint32_t* d, uint32_t a) {
    asm volatile("ldmatrix.sync.aligned.m8n8.x4.shared.b16 {%0,%1,%2,%3}, [%4];"
        : "=r"(d[0]), "=r"(d[1]), "=r"(d[2]), "=r"(d[3]) : "r"(a));
}
__device__ __forceinline__ void ldm_x4t(uint32_t* d, uint32_t a) {
    asm volatile("ldmatrix.sync.aligned.m8n8.x4.trans.shared.b16 {%0,%1,%2,%3}, [%4];"
        : "=r"(d[0]), "=r"(d[1]), "=r"(d[2]), "=r"(d[3]) : "r"(a));
}
__device__ __forceinline__ void mma16816(float* c, const uint32_t* a, const uint32_t* b) {
    asm volatile("mma.sync.aligned.m16n8k16.row.col.f32.bf16.bf16.f32 "
        "{%0,%1,%2,%3}, {%4,%5,%6,%7}, {%8,%9}, {%0,%1,%2,%3};"
        : "+f"(c[0]), "+f"(c[1]), "+f"(c[2]), "+f"(c[3])
        : "r"(a[0]), "r"(a[1]), "r"(a[2]), "r"(a[3]), "r"(b[0]), "r"(b[1]));
}
__device__ __forceinline__ uint32_t pack2bf(float a, float b) {
    __nv_bfloat16 ha = __float2bfloat16(a), hb = __float2bfloat16(b);
    return (uint32_t)__bfloat16_as_ushort(ha) | ((uint32_t)__bfloat16_as_ushort(hb) << 16);
}
__device__ __forceinline__ void split2(float2 v, uint32_t& hw, uint32_t& lw) {
    __nv_bfloat16 h0 = __float2bfloat16(v.x), h1 = __float2bfloat16(v.y);
    hw = (uint32_t)__bfloat16_as_ushort(h0) | ((uint32_t)__bfloat16_as_ushort(h1) << 16);
    lw = pack2bf(v.x - __bfloat162float(h0), v.y - __bfloat162float(h1));
}

/* ---- prologue kernel: fp32 K/V -> swizzled bf16 hi/lo tiles ---- */
__global__ __launch_bounds__(256)
void conv_kv_kernel(const float* __restrict__ Kg, const float* __restrict__ Vg)
{
    int gid = blockIdx.x * 256 + threadIdx.x;      /* 65536 threads */
    int b = gid >> 10, key = gid & 1023;
    int kt = key >> 6, row = key & 63;
    size_t tb = (size_t)(b * NTILE + kt) * 8192;
    const float2* ks = (const float2*)(Kg + ((size_t)(b * LKS + key)) * DIMS);
    const float2* vs = (const float2*)(Vg + ((size_t)(b * LKS + key)) * DIMS);
    char* khi = (char*)g_Khi + tb; char* klo = (char*)g_Klo + tb;
    char* vhi = (char*)g_Vhi + tb; char* vlo = (char*)g_Vlo + tb;
    #pragma unroll
    for (int q = 0; q < 16; ++q) {
        uint32_t off = SWZ((uint32_t)(row * 128 + q * 8));
        uint32_t h0, l0, h1, l1;
        split2(ks[2 * q], h0, l0); split2(ks[2 * q + 1], h1, l1);
        *(uint2*)(khi + off) = make_uint2(h0, h1);
        *(uint2*)(klo + off) = make_uint2(l0, l1);
        split2(vs[2 * q], h0, l0); split2(vs[2 * q + 1], h1, l1);
        *(uint2*)(vhi + off) = make_uint2(h0, h1);
        *(uint2*)(vlo + off) = make_uint2(l0, l1);
    }
}

/* issue cp.asyncs for one KV tile (8 x 16B per thread) */
__device__ __forceinline__ void issue_kv(uint32_t dst, size_t tile, int tid) {
    const char* skhi = (const char*)g_Khi + tile * 8192;
    const char* sklo = (const char*)g_Klo + tile * 8192;
    const char* svhi = (const char*)g_Vhi + tile * 8192;
    const char* svlo = (const char*)g_Vlo + tile * 8192;
    #pragma unroll
    for (int ii = 0; ii < 2; ++ii) {
        int i = (tid + 256 * ii) * 16;
        cp16(dst + i,         skhi + i);
        cp16(dst + 8192 + i,  sklo + i);
        cp16(dst + 16384 + i, svhi + i);
        cp16(dst + 24576 + i, svlo + i);
    }
}

/* ============================ main kernel ============================ */
__global__ __launch_bounds__(NTHREADS, 2)
void attn_mma_kernel(const float* __restrict__ Qg,
                     const int* __restrict__ qmask, const int* __restrict__ kmask,
                     const int* __restrict__ gmask,
                     float* __restrict__ out_av, float* __restrict__ out_attn)
{
    extern __shared__ char smem[];
    const uint32_t sb = smem_u32(smem);
    float* sLH  = (float*)(smem + OFF_SLH);
    float* sInv = (float*)(smem + OFF_SINV);

    const int tid  = threadIdx.x;
    const int warp = tid >> 5;
    const int lane = tid & 31;
    const int l16  = lane & 15;
    const int qg   = lane & 3;
    const int r    = lane >> 2;
    const int p    = warp >> 1;     /* pair 0..3 */
    const int h    = warp & 1;      /* key-half / d-half */
    const int b    = blockIdx.y;
    const int q0   = blockIdx.x * LQT;

    const int* kmb = kmask + (size_t)b * LKS;
    const int row_r  = p * 16 + r;
    const int row_r8 = row_r + 8;
    const size_t gq_r  = (size_t)(b * LQS + q0 + row_r);
    const size_t gq_r8 = gq_r + 8;
    const int* gm_r  = gmask + gq_r  * LKS;
    const int* gm_r8 = gmask + gq_r8 * LKS;
    float* attn_r  = out_attn + gq_r  * LKS;
    float* attn_r8 = out_attn + gq_r8 * LKS;

    /* prologue: kv tile 0 */
    issue_kv(sb + OFF_KV, (size_t)(b * NTILE), tid);
    CP_COMMIT();

    /* stage Q (scaled 1/8), split hi/lo, SW128 */
    {
        const float4* Qg4 = (const float4*)(Qg + ((size_t)(b * LQS + q0)) * DIMS);
        #pragma unroll
        for (int i = 0; i < 4; ++i) {
            int idx = tid + 256 * i;                 /* 1024 float4 */
            int row = idx >> 4, dp4 = idx & 15;
            float4 v = Qg4[idx];
            v.x *= 0.125f; v.y *= 0.125f; v.z *= 0.125f; v.w *= 0.125f;
            uint32_t h0, l0, h1, l1;
            split2(make_float2(v.x, v.y), h0, l0);
            split2(make_float2(v.z, v.w), h1, l1);
            uint32_t off = SWZ((uint32_t)(row * 128 + dp4 * 8));
            *(uint2*)(smem + OFF_Q   + off) = make_uint2(h0, h1);
            *(uint2*)(smem + OFF_QLO + off) = make_uint2(l0, l1);
        }
    }

    /* gmask prefetch tile 0 into registers */
    int2 gc[4], gc8[4];
    #pragma unroll
    for (int j = 0; j < 4; ++j) {
        const int c = h * 32 + j * 8 + 2 * qg;
        gc[j]  = __ldg((const int2*)(gm_r  + c));
        gc8[j] = __ldg((const int2*)(gm_r8 + c));
    }

    float oc[4][4];
    #pragma unroll
    for (int j = 0; j < 4; ++j)
        #pragma unroll
        for (int c = 0; c < 4; ++c) oc[j][c] = 0.f;
    float l0s = 0.f, l1s = 0.f;

    const uint32_t Pb_hi = OFF_P + (uint32_t)(p * 4096);
    const uint32_t Pb_lo = Pb_hi + 2048;

    #pragma unroll 1
    for (int kt = 0; kt < NTILE; ++kt) {
        const int kbase = kt * BKT;
        const uint32_t cb = OFF_KV + (uint32_t)((kt & 1) * KV_BYTES);

        __syncthreads();    /* prev PV done -> safe to overwrite other buffer */
        if (kt + 1 < NTILE)
            issue_kv(sb + OFF_KV + (uint32_t)(((kt + 1) & 1) * KV_BYTES),
                     (size_t)(b * NTILE + kt + 1), tid);
        CP_COMMIT();

        /* gmask prefetch for next tile (regular LDG, consumed next iter) */
        int2 gn[4], gn8[4];
        if (kt + 1 < NTILE) {
            const int nb = kbase + BKT;
            #pragma unroll
            for (int j = 0; j < 4; ++j) {
                const int c = nb + h * 32 + j * 8 + 2 * qg;
                gn[j]  = __ldg((const int2*)(gm_r  + c));
                gn8[j] = __ldg((const int2*)(gm_r8 + c));
            }
        }

        asm volatile("cp.async.wait_group 1;" ::: "memory");
        __syncthreads();    /* kv(kt) visible */

        /* ---- S = Q K^T for this warp's 32-key half (bf16 EC) ---- */
        float sc[4][4];
        #pragma unroll
        for (int j = 0; j < 4; ++j)
            #pragma unroll
            for (int c = 0; c < 4; ++c) sc[j][c] = 0.f;

        #pragma unroll
        for (int t = 0; t < 4; ++t) {
            uint32_t qh4[4], ql4[4];
            uint32_t offq = SWZ((uint32_t)((p * 16 + l16) * 128 + t * 32 + (lane >> 4) * 16));
            ldm_x4(qh4, sb + OFF_Q   + offq);
            ldm_x4(ql4, sb + OFF_QLO + offq);
            #pragma unroll
            for (int jp = 0; jp < 2; ++jp) {
                uint32_t kh4[4], kl4[4];
                int krow = h * 32 + jp * 16 + (lane & 7) + ((lane >> 4) << 3);
                uint32_t off = SWZ((uint32_t)(krow * 128 + t * 32 + ((lane >> 3) & 1) * 16));
                ldm_x4(kh4, sb + cb + off);          /* Khi */
                ldm_x4(kl4, sb + cb + 8192 + off);   /* Klo */
                mma16816(sc[2*jp],   qh4, kh4);
                mma16816(sc[2*jp],   ql4, kh4);
                mma16816(sc[2*jp],   qh4, kl4);
                mma16816(sc[2*jp+1], qh4, kh4 + 2);
                mma16816(sc[2*jp+1], ql4, kh4 + 2);
                mma16816(sc[2*jp+1], qh4, kl4 + 2);
            }
        }

        /* ---- epilogue: mask+exp+attn STG+P pack to smem ---- */
        #pragma unroll
        for (int j = 0; j < 4; ++j) {
            const int c = h * 32 + j * 8 + 2 * qg;
            const int gcol = kbase + c;
            int2 km = __ldg((const int2*)(kmb + gcol));
            float e0 = (km.x && gc[j].x)  ? __expf(sc[j][0]) : 0.f;
            float e1 = (km.y && gc[j].y)  ? __expf(sc[j][1]) : 0.f;
            float e2 = (km.x && gc8[j].x) ? __expf(sc[j][2]) : 0.f;
            float e3 = (km.y && gc8[j].y) ? __expf(sc[j][3]) : 0.f;
            l0s += e0 + e1; l1s += e2 + e3;
            *(float2*)(attn_r  + gcol) = make_float2(e0, e1);
            *(float2*)(attn_r8 + gcol) = make_float2(e2, e3);
            uint32_t hw, lw;
            uint32_t offr  = SWZ((uint32_t)(r  * 128 + c * 2));
            uint32_t offr8 = SWZ((uint32_t)((r + 8) * 128 + c * 2));
            split2(make_float2(e0, e1), hw, lw);
            *(uint32_t*)(smem + Pb_hi + offr)  = hw;
            *(uint32_t*)(smem + Pb_lo + offr)  = lw;
            split2(make_float2(e2, e3), hw, lw);
            *(uint32_t*)(smem + Pb_hi + offr8) = hw;
            *(uint32_t*)(smem + Pb_lo + offr8) = lw;
        }

        /* pair barrier: P tile complete (2 warps, 64 threads) */
        asm volatile("bar.sync %0, 64;" :: "r"(1 + p) : "memory");

        /* ---- PV: O[16 x 32d-half] over all 64 keys (bf16 EC) ---- */
        #pragma unroll
        for (int ks = 0; ks < 4; ++ks) {
            uint32_t pah4[4], pal4[4];
            uint32_t offp = SWZ((uint32_t)(l16 * 128 + ks * 32 + (lane >> 4) * 16));
            ldm_x4(pah4, sb + Pb_hi + offp);
            ldm_x4(pal4, sb + Pb_lo + offp);
            #pragma unroll
            for (int j2p = 0; j2p < 2; ++j2p) {
                uint32_t vh4[4], vl4[4];
                uint32_t offv = SWZ((uint32_t)((ks * 16 + l16) * 128 +
                                               h * 64 + j2p * 32 + (lane >> 4) * 16));
                ldm_x4t(vh4, sb + cb + 16384 + offv);   /* Vhi */
                ldm_x4t(vl4, sb + cb + 24576 + offv);   /* Vlo */
                mma16816(oc[2*j2p],   pah4, vh4);
                mma16816(oc[2*j2p],   pah4, vl4);
                mma16816(oc[2*j2p],   pal4, vh4);
                mma16816(oc[2*j2p+1], pah4, vh4 + 2);
                mma16816(oc[2*j2p+1], pah4, vl4 + 2);
                mma16816(oc[2*j2p+1], pal4, vh4 + 2);
            }
        }

        if (kt + 1 < NTILE) {
            #pragma unroll
            for (int j = 0; j < 4; ++j) { gc[j] = gn[j]; gc8[j] = gn8[j]; }
        }
    }

    /* ---- half row sums -> inv ---- */
    l0s += __shfl_xor_sync(0xffffffffu, l0s, 1);
    l0s += __shfl_xor_sync(0xffffffffu, l0s, 2);
    l1s += __shfl_xor_sync(0xffffffffu, l1s, 1);
    l1s += __shfl_xor_sync(0xffffffffu, l1s, 2);
    if (qg == 0) {
        sLH[h * 64 + row_r]  = l0s;
        sLH[h * 64 + row_r8] = l1s;
    }
    __syncthreads();
    if (tid < LQT) {
        float l = sLH[tid] + sLH[64 + tid];
        sInv[tid] = (qmask[(size_t)b * LQS + q0 + tid] != 0) ? (1.0f / l) : 0.0f;
    }
    __threadfence_block();
    __syncthreads();

    /* ---- store attn_value (own d-half) ---- */
    {
        const float inv0 = sInv[row_r];
        const float inv1 = sInv[row_r8];
        float* av_r  = out_av + gq_r  * DIMS;
        float* av_r8 = out_av + gq_r8 * DIMS;
        #pragma unroll
        for (int jj = 0; jj < 4; ++jj) {
            const int col = h * 32 + jj * 8 + 2 * qg;
            *(float2*)(av_r  + col) = make_float2(oc[jj][0] * inv0, oc[jj][1] * inv0);
            *(float2*)(av_r8 + col) = make_float2(oc[jj][2] * inv1, oc[jj][3] * inv1);
        }
    }

    /* ---- fused normalize of this CTA's attn rows ---- */
    {
        float4* base = (float4*)(out_attn + ((size_t)(b * LQS + q0)) * LKS);
        for (int i = tid; i < LQT * 256; i += NTHREADS) {
            const float inv = sInv[i >> 8];
            float4 v = base[i];
            v.x *= inv; v.y *= inv; v.z *= inv; v.w *= inv;
            base[i] = v;
        }
    }
}

extern "C" void kernel_launch(void* const* d_in, const int* in_sizes, int n_in,
                              void* d_out, int out_size) {
    const float* Q  = (const float*)d_in[0];
    const float* K  = (const float*)d_in[1];
    const float* V  = (const float*)d_in[2];
    const int*   qm = (const int*)d_in[3];
    const int*   km = (const int*)d_in[4];
    const int*   mk = (const int*)d_in[5];

    const long long NAV = (long long)BATCH * LQS * DIMS;
    float* out  = (float*)d_out;
    float* av   = out;
    float* attn = out + NAV;
    (void)out_size; (void)in_sizes; (void)n_in;

    conv_kv_kernel<<<BATCH * LKS / 256, 256>>>(K, V);

    cudaFuncSetAttribute(attn_mma_kernel, cudaFuncAttributeMaxDynamicSharedMemorySize,
                         SMEM_BYTES);
    dim3 grid(LQS / LQT, BATCH);
    attn_mma_kernel<<<grid, NTHREADS, SMEM_BYTES>>>(Q, qm, km, mk, av, attn);
}

// round 13
// speedup vs baseline: 1.1952x; 1.1141x over previous
#include <cuda_runtime.h>
#include <cuda_bf16.h>
#include <cuda_fp16.h>
#include <cstdint>

#define BATCH 64
#define LQS   1024
#define LKS   1024
#define DIMS  64
#define NTHREADS 256
#define LQT   64        /* q-rows per CTA (4 pairs x 16) */
#define BKT   64        /* keys per tile */
#define NTILE 16

/* ---- shared memory byte offsets ---- */
#define OFF_SLH  0                      /* 2 x 64 floats: half row sums */
#define OFF_SINV 512                    /* 64 floats: inv */
#define OFF_Q    1024                   /* Qhi 8K */
#define OFF_QLO  (OFF_Q + 8192)         /* Qlo 8K */
#define OFF_KV   17408                  /* ring: 2 x 32K (Khi,Klo,Vhi,Vlo 8K each) */
#define KV_BYTES 32768
#define OFF_P    (OFF_KV + 2 * KV_BYTES)    /* 82944: 4 pairs x 2K (fp16 P) */
#define SMEM_BYTES (OFF_P + 8192)           /* 91136 */

#define SWZ(x) ((x) ^ (((x) >> 3) & 0x70))

/* ---- global scratch: pre-swizzled K (bf16 hi/lo) and V (fp16 hi/lo) tiles ---- */
__device__ uint4 g_Khi[BATCH * NTILE * 512];
__device__ uint4 g_Klo[BATCH * NTILE * 512];
__device__ uint4 g_Vhi[BATCH * NTILE * 512];
__device__ uint4 g_Vlo[BATCH * NTILE * 512];

/* ------------------------- helpers ------------------------- */
__device__ __forceinline__ uint32_t smem_u32(const void* p) {
    uint32_t a;
    asm("{ .reg .u64 t; cvta.to.shared.u64 t, %1; cvt.u32.u64 %0, t; }" : "=r"(a) : "l"(p));
    return a;
}
__device__ __forceinline__ void cp16(uint32_t d, const void* s) {
    asm volatile("cp.async.cg.shared.global [%0], [%1], 16;" :: "r"(d), "l"(s) : "memory");
}
#define CP_COMMIT() asm volatile("cp.async.commit_group;" ::: "memory")
__device__ __forceinline__ void ldm_x4(uint32_t* d, uint32_t a) {
    asm volatile("ldmatrix.sync.aligned.m8n8.x4.shared.b16 {%0,%1,%2,%3}, [%4];"
        : "=r"(d[0]), "=r"(d[1]), "=r"(d[2]), "=r"(d[3]) : "r"(a));
}
__device__ __forceinline__ void ldm_x4t(uint32_t* d, uint32_t a) {
    asm volatile("ldmatrix.sync.aligned.m8n8.x4.trans.shared.b16 {%0,%1,%2,%3}, [%4];"
        : "=r"(d[0]), "=r"(d[1]), "=r"(d[2]), "=r"(d[3]) : "r"(a));
}
__device__ __forceinline__ void mma_bf16(float* c, const uint32_t* a, const uint32_t* b) {
    asm volatile("mma.sync.aligned.m16n8k16.row.col.f32.bf16.bf16.f32 "
        "{%0,%1,%2,%3}, {%4,%5,%6,%7}, {%8,%9}, {%0,%1,%2,%3};"
        : "+f"(c[0]), "+f"(c[1]), "+f"(c[2]), "+f"(c[3])
        : "r"(a[0]), "r"(a[1]), "r"(a[2]), "r"(a[3]), "r"(b[0]), "r"(b[1]));
}
__device__ __forceinline__ void mma_f16(float* c, const uint32_t* a, const uint32_t* b) {
    asm volatile("mma.sync.aligned.m16n8k16.row.col.f32.f16.f16.f32 "
        "{%0,%1,%2,%3}, {%4,%5,%6,%7}, {%8,%9}, {%0,%1,%2,%3};"
        : "+f"(c[0]), "+f"(c[1]), "+f"(c[2]), "+f"(c[3])
        : "r"(a[0]), "r"(a[1]), "r"(a[2]), "r"(a[3]), "r"(b[0]), "r"(b[1]));
}
__device__ __forceinline__ uint32_t pack2bf(float a, float b) {
    __nv_bfloat16 ha = __float2bfloat16(a), hb = __float2bfloat16(b);
    return (uint32_t)__bfloat16_as_ushort(ha) | ((uint32_t)__bfloat16_as_ushort(hb) << 16);
}
__device__ __forceinline__ void split2(float2 v, uint32_t& hw, uint32_t& lw) {
    __nv_bfloat16 h0 = __float2bfloat16(v.x), h1 = __float2bfloat16(v.y);
    hw = (uint32_t)__bfloat16_as_ushort(h0) | ((uint32_t)__bfloat16_as_ushort(h1) << 16);
    lw = pack2bf(v.x - __bfloat162float(h0), v.y - __bfloat162float(h1));
}
__device__ __forceinline__ uint32_t pack2h(float a, float b) {
    __half ha = __float2half_rn(a), hb = __float2half_rn(b);
    return (uint32_t)__half_as_ushort(ha) | ((uint32_t)__half_as_ushort(hb) << 16);
}
__device__ __forceinline__ void split2h(float2 v, uint32_t& hw, uint32_t& lw) {
    __half h0 = __float2half_rn(v.x), h1 = __float2half_rn(v.y);
    hw = (uint32_t)__half_as_ushort(h0) | ((uint32_t)__half_as_ushort(h1) << 16);
    lw = pack2h(v.x - __half2float(h0), v.y - __half2float(h1));
}

/* ---- prologue kernel: K -> bf16 hi/lo, V -> fp16 hi/lo, swizzled (coalesced) ---- */
__global__ __launch_bounds__(256)
void conv_kv_kernel(const float* __restrict__ Kg, const float* __restrict__ Vg)
{
    const int tile = blockIdx.x;            /* 0..1023 = b*16+kt */
    const size_t tb = (size_t)tile * 8192;
    const size_t srow0 = (size_t)tile * 64; /* first key row of tile */
    #pragma unroll
    for (int it = 0; it < 4; ++it) {
        int item = threadIdx.x + 256 * it;  /* 0..1023 */
        int arr = item >> 9;                /* 0:K 1:V */
        int row = (item >> 3) & 63;
        int dg  = item & 7;
        const float4* src = (const float4*)((arr ? Vg : Kg) + (srow0 + row) * DIMS + dg * 8);
        float4 a = src[0], c = src[1];
        uint32_t h0, l0, h1, l1, h2, l2, h3, l3;
        if (arr) {
            split2h(make_float2(a.x, a.y), h0, l0);
            split2h(make_float2(a.z, a.w), h1, l1);
            split2h(make_float2(c.x, c.y), h2, l2);
            split2h(make_float2(c.z, c.w), h3, l3);
        } else {
            split2(make_float2(a.x, a.y), h0, l0);
            split2(make_float2(a.z, a.w), h1, l1);
            split2(make_float2(c.x, c.y), h2, l2);
            split2(make_float2(c.z, c.w), h3, l3);
        }
        uint32_t off = SWZ((uint32_t)(row * 128 + dg * 16));
        char* hi = (char*)(arr ? g_Vhi : g_Khi) + tb;
        char* lo = (char*)(arr ? g_Vlo : g_Klo) + tb;
        *(uint4*)(hi + off) = make_uint4(h0, h1, h2, h3);
        *(uint4*)(lo + off) = make_uint4(l0, l1, l2, l3);
    }
}

/* issue cp.asyncs for one KV tile (8 x 16B per thread) */
__device__ __forceinline__ void issue_kv(uint32_t dst, size_t tile, int tid) {
    const char* skhi = (const char*)g_Khi + tile * 8192;
    const char* sklo = (const char*)g_Klo + tile * 8192;
    const char* svhi = (const char*)g_Vhi + tile * 8192;
    const char* svlo = (const char*)g_Vlo + tile * 8192;
    #pragma unroll
    for (int ii = 0; ii < 2; ++ii) {
        int i = (tid + 256 * ii) * 16;
        cp16(dst + i,         skhi + i);
        cp16(dst + 8192 + i,  sklo + i);
        cp16(dst + 16384 + i, svhi + i);
        cp16(dst + 24576 + i, svlo + i);
    }
}

/* ============================ main kernel ============================ */
__global__ __launch_bounds__(NTHREADS, 2)
void attn_mma_kernel(const float* __restrict__ Qg,
                     const int* __restrict__ qmask, const int* __restrict__ kmask,
                     const int* __restrict__ gmask,
                     float* __restrict__ out_av, float* __restrict__ out_attn)
{
    extern __shared__ char smem[];
    const uint32_t sb = smem_u32(smem);
    float* sLH  = (float*)(smem + OFF_SLH);
    float* sInv = (float*)(smem + OFF_SINV);

    const int tid  = threadIdx.x;
    const int warp = tid >> 5;
    const int lane = tid & 31;
    const int l16  = lane & 15;
    const int qg   = lane & 3;
    const int r    = lane >> 2;
    const int p    = warp >> 1;     /* pair 0..3 */
    const int h    = warp & 1;      /* key-half / d-half */
    const int b    = blockIdx.y;
    const int q0   = blockIdx.x * LQT;

    const int* kmb = kmask + (size_t)b * LKS;
    const int row_r  = p * 16 + r;
    const int row_r8 = row_r + 8;
    const size_t gq_r  = (size_t)(b * LQS + q0 + row_r);
    const size_t gq_r8 = gq_r + 8;
    const int* gm_r  = gmask + gq_r  * LKS;
    const int* gm_r8 = gmask + gq_r8 * LKS;
    float* attn_r  = out_attn + gq_r  * LKS;
    float* attn_r8 = out_attn + gq_r8 * LKS;

    /* prologue: kv tile 0 */
    issue_kv(sb + OFF_KV, (size_t)(b * NTILE), tid);
    CP_COMMIT();

    /* stage Q (scaled 1/8), split hi/lo bf16, SW128 */
    {
        const float4* Qg4 = (const float4*)(Qg + ((size_t)(b * LQS + q0)) * DIMS);
        #pragma unroll
        for (int i = 0; i < 4; ++i) {
            int idx = tid + 256 * i;                 /* 1024 float4 */
            int row = idx >> 4, dp4 = idx & 15;
            float4 v = Qg4[idx];
            v.x *= 0.125f; v.y *= 0.125f; v.z *= 0.125f; v.w *= 0.125f;
            uint32_t h0, l0, h1, l1;
            split2(make_float2(v.x, v.y), h0, l0);
            split2(make_float2(v.z, v.w), h1, l1);
            uint32_t off = SWZ((uint32_t)(row * 128 + dp4 * 8));
            *(uint2*)(smem + OFF_Q   + off) = make_uint2(h0, h1);
            *(uint2*)(smem + OFF_QLO + off) = make_uint2(l0, l1);
        }
    }

    /* gmask prefetch tile 0 into registers */
    int2 gc[4], gc8[4];
    #pragma unroll
    for (int j = 0; j < 4; ++j) {
        const int c = h * 32 + j * 8 + 2 * qg;
        gc[j]  = __ldg((const int2*)(gm_r  + c));
        gc8[j] = __ldg((const int2*)(gm_r8 + c));
    }

    float oc[4][4];
    #pragma unroll
    for (int j = 0; j < 4; ++j)
        #pragma unroll
        for (int c = 0; c < 4; ++c) oc[j][c] = 0.f;
    float l0s = 0.f, l1s = 0.f;

    const uint32_t Pb = OFF_P + (uint32_t)(p * 2048);

    #pragma unroll 1
    for (int kt = 0; kt < NTILE; ++kt) {
        const int kbase = kt * BKT;
        const uint32_t cb = OFF_KV + (uint32_t)((kt & 1) * KV_BYTES);

        __syncthreads();    /* prev PV done -> safe to overwrite other buffer */
        if (kt + 1 < NTILE)
            issue_kv(sb + OFF_KV + (uint32_t)(((kt + 1) & 1) * KV_BYTES),
                     (size_t)(b * NTILE + kt + 1), tid);
        CP_COMMIT();

        /* gmask prefetch for next tile (regular LDG, consumed next iter) */
        int2 gn[4], gn8[4];
        if (kt + 1 < NTILE) {
            const int nb = kbase + BKT;
            #pragma unroll
            for (int j = 0; j < 4; ++j) {
                const int c = nb + h * 32 + j * 8 + 2 * qg;
                gn[j]  = __ldg((const int2*)(gm_r  + c));
                gn8[j] = __ldg((const int2*)(gm_r8 + c));
            }
        }

        asm volatile("cp.async.wait_group 1;" ::: "memory");
        __syncthreads();    /* kv(kt) visible */

        /* ---- S = Q K^T for this warp's 32-key half (bf16 EC, 3-pass) ---- */
        float sc[4][4];
        #pragma unroll
        for (int j = 0; j < 4; ++j)
            #pragma unroll
            for (int c = 0; c < 4; ++c) sc[j][c] = 0.f;

        #pragma unroll
        for (int t = 0; t < 4; ++t) {
            uint32_t qh4[4], ql4[4];
            uint32_t offq = SWZ((uint32_t)((p * 16 + l16) * 128 + t * 32 + (lane >> 4) * 16));
            ldm_x4(qh4, sb + OFF_Q   + offq);
            ldm_x4(ql4, sb + OFF_QLO + offq);
            #pragma unroll
            for (int jp = 0; jp < 2; ++jp) {
                uint32_t kh4[4], kl4[4];
                int krow = h * 32 + jp * 16 + (lane & 7) + ((lane >> 4) << 3);
                uint32_t off = SWZ((uint32_t)(krow * 128 + t * 32 + ((lane >> 3) & 1) * 16));
                ldm_x4(kh4, sb + cb + off);          /* Khi */
                ldm_x4(kl4, sb + cb + 8192 + off);   /* Klo */
                mma_bf16(sc[2*jp],   qh4, kh4);
                mma_bf16(sc[2*jp],   ql4, kh4);
                mma_bf16(sc[2*jp],   qh4, kl4);
                mma_bf16(sc[2*jp+1], qh4, kh4 + 2);
                mma_bf16(sc[2*jp+1], ql4, kh4 + 2);
                mma_bf16(sc[2*jp+1], qh4, kl4 + 2);
            }
        }

        /* ---- epilogue: mask+exp+attn STG+P(fp16) pack to smem ---- */
        #pragma unroll
        for (int j = 0; j < 4; ++j) {
            const int c = h * 32 + j * 8 + 2 * qg;
            const int gcol = kbase + c;
            int2 km = __ldg((const int2*)(kmb + gcol));
            float e0 = (km.x && gc[j].x)  ? __expf(sc[j][0]) : 0.f;
            float e1 = (km.y && gc[j].y)  ? __expf(sc[j][1]) : 0.f;
            float e2 = (km.x && gc8[j].x) ? __expf(sc[j][2]) : 0.f;
            float e3 = (km.y && gc8[j].y) ? __expf(sc[j][3]) : 0.f;
            l0s += e0 + e1; l1s += e2 + e3;
            *(float2*)(attn_r  + gcol) = make_float2(e0, e1);
            *(float2*)(attn_r8 + gcol) = make_float2(e2, e3);
            uint32_t offr  = SWZ((uint32_t)(r  * 128 + c * 2));
            uint32_t offr8 = SWZ((uint32_t)((r + 8) * 128 + c * 2));
            *(uint32_t*)(smem + Pb + offr)  = pack2h(e0, e1);
            *(uint32_t*)(smem + Pb + offr8) = pack2h(e2, e3);
        }

        /* pair barrier: P tile complete (2 warps, 64 threads) */
        asm volatile("bar.sync %0, 64;" :: "r"(1 + p) : "memory");

        /* ---- PV: O[16 x 32d-half] over all 64 keys (fp16: Ph*Vh + Ph*Vl) ---- */
        #pragma unroll
        for (int ks = 0; ks < 4; ++ks) {
            uint32_t pah4[4];
            uint32_t offp = SWZ((uint32_t)(l16 * 128 + ks * 32 + (lane >> 4) * 16));
            ldm_x4(pah4, sb + Pb + offp);
            #pragma unroll
            for (int j2p = 0; j2p < 2; ++j2p) {
                uint32_t vh4[4], vl4[4];
                uint32_t offv = SWZ((uint32_t)((ks * 16 + l16) * 128 +
                                               h * 64 + j2p * 32 + (lane >> 4) * 16));
                ldm_x4t(vh4, sb + cb + 16384 + offv);   /* Vhi */
                ldm_x4t(vl4, sb + cb + 24576 + offv);   /* Vlo */
                mma_f16(oc[2*j2p],   pah4, vh4);
                mma_f16(oc[2*j2p],   pah4, vl4);
                mma_f16(oc[2*j2p+1], pah4, vh4 + 2);
                mma_f16(oc[2*j2p+1], pah4, vl4 + 2);
            }
        }

        if (kt + 1 < NTILE) {
            #pragma unroll
            for (int j = 0; j < 4; ++j) { gc[j] = gn[j]; gc8[j] = gn8[j]; }
        }
    }

    /* ---- half row sums -> inv ---- */
    l0s += __shfl_xor_sync(0xffffffffu, l0s, 1);
    l0s += __shfl_xor_sync(0xffffffffu, l0s, 2);
    l1s += __shfl_xor_sync(0xffffffffu, l1s, 1);
    l1s += __shfl_xor_sync(0xffffffffu, l1s, 2);
    if (qg == 0) {
        sLH[h * 64 + row_r]  = l0s;
        sLH[h * 64 + row_r8] = l1s;
    }
    __syncthreads();
    if (tid < LQT) {
        float l = sLH[tid] + sLH[64 + tid];
        sInv[tid] = (qmask[(size_t)b * LQS + q0 + tid] != 0) ? (1.0f / l) : 0.0f;
    }
    __threadfence_block();
    __syncthreads();

    /* ---- store attn_value (own d-half) ---- */
    {
        const float inv0 = sInv[row_r];
        const float inv1 = sInv[row_r8];
        float* av_r  = out_av + gq_r  * DIMS;
        float* av_r8 = out_av + gq_r8 * DIMS;
        #pragma unroll
        for (int jj = 0; jj < 4; ++jj) {
            const int col = h * 32 + jj * 8 + 2 * qg;
            *(float2*)(av_r  + col) = make_float2(oc[jj][0] * inv0, oc[jj][1] * inv0);
            *(float2*)(av_r8 + col) = make_float2(oc[jj][2] * inv1, oc[jj][3] * inv1);
        }
    }

    /* ---- fused normalize of this CTA's attn rows ---- */
    {
        float4* base = (float4*)(out_attn + ((size_t)(b * LQS + q0)) * LKS);
        for (int i = tid; i < LQT * 256; i += NTHREADS) {
            const float inv = sInv[i >> 8];
            float4 v = base[i];
            v.x *= inv; v.y *= inv; v.z *= inv; v.w *= inv;
            base[i] = v;
        }
    }
}

extern "C" void kernel_launch(void* const* d_in, const int* in_sizes, int n_in,
                              void* d_out, int out_size) {
    const float* Q  = (const float*)d_in[0];
    const float* K  = (const float*)d_in[1];
    const float* V  = (const float*)d_in[2];
    const int*   qm = (const int*)d_in[3];
    const int*   km = (const int*)d_in[4];
    const int*   mk = (const int*)d_in[5];

    const long long NAV = (long long)BATCH * LQS * DIMS;
    float* out  = (float*)d_out;
    float* av   = out;
    float* attn = out + NAV;
    (void)out_size; (void)in_sizes; (void)n_in;

    conv_kv_kernel<<<BATCH * NTILE, 256>>>(K, V);

    cudaFuncSetAttribute(attn_mma_kernel, cudaFuncAttributeMaxDynamicSharedMemorySize,
                         SMEM_BYTES);
    dim3 grid(LQS / LQT, BATCH);
    attn_mma_kernel<<<grid, NTHREADS, SMEM_BYTES>>>(Q, qm, km, mk, av, attn);
}

// round 14
// speedup vs baseline: 1.2973x; 1.0854x over previous
#include <cuda_runtime.h>
#include <cuda_bf16.h>
#include <cuda_fp16.h>
#include <cstdint>

#define BATCH 64
#define LQS   1024
#define LKS   1024
#define DIMS  64
#define NTHREADS 256
#define LQT   64        /* q-rows per CTA (4 pairs x 16) */
#define BKT   64        /* keys per tile */
#define NTILE 16

/* ---- shared memory byte offsets ---- */
#define OFF_SLH  0                      /* 2 x 64 floats: half row sums */
#define OFF_SINV 512                    /* 64 floats: inv */
#define OFF_Q    1024                   /* Qhi 8K */
#define OFF_QLO  (OFF_Q + 8192)         /* Qlo 8K */
#define OFF_KV   17408                  /* ring: 2 x 32K (Khi,Klo,Vhi,Vlo 8K each) */
#define KV_BYTES 32768
#define OFF_P    (OFF_KV + 2 * KV_BYTES)    /* 82944: 4 pairs x 2K (fp16 P) */
#define SMEM_BYTES (OFF_P + 8192)           /* 91136 */

#define SWZ(x) ((x) ^ (((x) >> 3) & 0x70))

/* ---- global scratch: pre-swizzled K (bf16 hi/lo) and V (fp16 hi/lo) tiles ---- */
__device__ uint4 g_Khi[BATCH * NTILE * 512];
__device__ uint4 g_Klo[BATCH * NTILE * 512];
__device__ uint4 g_Vhi[BATCH * NTILE * 512];
__device__ uint4 g_Vlo[BATCH * NTILE * 512];

/* ------------------------- helpers ------------------------- */
__device__ __forceinline__ uint32_t smem_u32(const void* p) {
    uint32_t a;
    asm("{ .reg .u64 t; cvta.to.shared.u64 t, %1; cvt.u32.u64 %0, t; }" : "=r"(a) : "l"(p));
    return a;
}
__device__ __forceinline__ void cp16(uint32_t d, const void* s) {
    asm volatile("cp.async.cg.shared.global [%0], [%1], 16;" :: "r"(d), "l"(s) : "memory");
}
#define CP_COMMIT() asm volatile("cp.async.commit_group;" ::: "memory")
__device__ __forceinline__ void ldm_x4(uint32_t* d, uint32_t a) {
    asm volatile("ldmatrix.sync.aligned.m8n8.x4.shared.b16 {%0,%1,%2,%3}, [%4];"
        : "=r"(d[0]), "=r"(d[1]), "=r"(d[2]), "=r"(d[3]) : "r"(a));
}
__device__ __forceinline__ void ldm_x4t(uint32_t* d, uint32_t a) {
    asm volatile("ldmatrix.sync.aligned.m8n8.x4.trans.shared.b16 {%0,%1,%2,%3}, [%4];"
        : "=r"(d[0]), "=r"(d[1]), "=r"(d[2]), "=r"(d[3]) : "r"(a));
}
__device__ __forceinline__ void mma_bf16(float* c, const uint32_t* a, const uint32_t* b) {
    asm volatile("mma.sync.aligned.m16n8k16.row.col.f32.bf16.bf16.f32 "
        "{%0,%1,%2,%3}, {%4,%5,%6,%7}, {%8,%9}, {%0,%1,%2,%3};"
        : "+f"(c[0]), "+f"(c[1]), "+f"(c[2]), "+f"(c[3])
        : "r"(a[0]), "r"(a[1]), "r"(a[2]), "r"(a[3]), "r"(b[0]), "r"(b[1]));
}
__device__ __forceinline__ void mma_f16(float* c, const uint32_t* a, const uint32_t* b) {
    asm volatile("mma.sync.aligned.m16n8k16.row.col.f32.f16.f16.f32 "
        "{%0,%1,%2,%3}, {%4,%5,%6,%7}, {%8,%9}, {%0,%1,%2,%3};"
        : "+f"(c[0]), "+f"(c[1]), "+f"(c[2]), "+f"(c[3])
        : "r"(a[0]), "r"(a[1]), "r"(a[2]), "r"(a[3]), "r"(b[0]), "r"(b[1]));
}
__device__ __forceinline__ uint32_t pack2bf(float a, float b) {
    __nv_bfloat16 ha = __float2bfloat16(a), hb = __float2bfloat16(b);
    return (uint32_t)__bfloat16_as_ushort(ha) | ((uint32_t)__bfloat16_as_ushort(hb) << 16);
}
__device__ __forceinline__ void split2(float2 v, uint32_t& hw, uint32_t& lw) {
    __nv_bfloat16 h0 = __float2bfloat16(v.x), h1 = __float2bfloat16(v.y);
    hw = (uint32_t)__bfloat16_as_ushort(h0) | ((uint32_t)__bfloat16_as_ushort(h1) << 16);
    lw = pack2bf(v.x - __bfloat162float(h0), v.y - __bfloat162float(h1));
}
__device__ __forceinline__ uint32_t pack2h(float a, float b) {
    __half ha = __float2half_rn(a), hb = __float2half_rn(b);
    return (uint32_t)__half_as_ushort(ha) | ((uint32_t)__half_as_ushort(hb) << 16);
}
__device__ __forceinline__ void split2h(float2 v, uint32_t& hw, uint32_t& lw) {
    __half h0 = __float2half_rn(v.x), h1 = __float2half_rn(v.y);
    hw = (uint32_t)__half_as_ushort(h0) | ((uint32_t)__half_as_ushort(h1) << 16);
    lw = pack2h(v.x - __half2float(h0), v.y - __half2float(h1));
}

/* ---- prologue kernel: K -> bf16 hi/lo, V -> fp16 hi/lo, swizzled (coalesced) ---- */
__global__ __launch_bounds__(256)
void conv_kv_kernel(const float* __restrict__ Kg, const float* __restrict__ Vg)
{
    const int tile = blockIdx.x;            /* 0..1023 = b*16+kt */
    const size_t tb = (size_t)tile * 8192;
    const size_t srow0 = (size_t)tile * 64; /* first key row of tile */
    #pragma unroll
    for (int it = 0; it < 4; ++it) {
        int item = threadIdx.x + 256 * it;  /* 0..1023 */
        int arr = item >> 9;                /* 0:K 1:V */
        int row = (item >> 3) & 63;
        int dg  = item & 7;
        const float4* src = (const float4*)((arr ? Vg : Kg) + (srow0 + row) * DIMS + dg * 8);
        float4 a = src[0], c = src[1];
        uint32_t h0, l0, h1, l1, h2, l2, h3, l3;
        if (arr) {
            split2h(make_float2(a.x, a.y), h0, l0);
            split2h(make_float2(a.z, a.w), h1, l1);
            split2h(make_float2(c.x, c.y), h2, l2);
            split2h(make_float2(c.z, c.w), h3, l3);
        } else {
            split2(make_float2(a.x, a.y), h0, l0);
            split2(make_float2(a.z, a.w), h1, l1);
            split2(make_float2(c.x, c.y), h2, l2);
            split2(make_float2(c.z, c.w), h3, l3);
        }
        uint32_t off = SWZ((uint32_t)(row * 128 + dg * 16));
        char* hi = (char*)(arr ? g_Vhi : g_Khi) + tb;
        char* lo = (char*)(arr ? g_Vlo : g_Klo) + tb;
        *(uint4*)(hi + off) = make_uint4(h0, h1, h2, h3);
        *(uint4*)(lo + off) = make_uint4(l0, l1, l2, l3);
    }
}

/* issue cp.asyncs for one KV tile (8 x 16B per thread) */
__device__ __forceinline__ void issue_kv(uint32_t dst, size_t tile, int tid) {
    const char* skhi = (const char*)g_Khi + tile * 8192;
    const char* sklo = (const char*)g_Klo + tile * 8192;
    const char* svhi = (const char*)g_Vhi + tile * 8192;
    const char* svlo = (const char*)g_Vlo + tile * 8192;
    #pragma unroll
    for (int ii = 0; ii < 2; ++ii) {
        int i = (tid + 256 * ii) * 16;
        cp16(dst + i,         skhi + i);
        cp16(dst + 8192 + i,  sklo + i);
        cp16(dst + 16384 + i, svhi + i);
        cp16(dst + 24576 + i, svlo + i);
    }
}

/* ============================ main kernel ============================ */
__global__ __launch_bounds__(NTHREADS, 2)
void attn_mma_kernel(const float* __restrict__ Qg,
                     const int* __restrict__ qmask, const int* __restrict__ kmask,
                     const int* __restrict__ gmask,
                     float* __restrict__ out_av, float* __restrict__ out_attn)
{
    extern __shared__ char smem[];
    const uint32_t sb = smem_u32(smem);
    float* sLH  = (float*)(smem + OFF_SLH);
    float* sInv = (float*)(smem + OFF_SINV);

    const int tid  = threadIdx.x;
    const int warp = tid >> 5;
    const int lane = tid & 31;
    const int l16  = lane & 15;
    const int qg   = lane & 3;
    const int r    = lane >> 2;
    const int p    = warp >> 1;     /* pair 0..3 */
    const int h    = warp & 1;      /* key-half / d-half */
    const int b    = blockIdx.y;
    const int q0   = blockIdx.x * LQT;

    const int* kmb = kmask + (size_t)b * LKS;
    const int row_r  = p * 16 + r;
    const int row_r8 = row_r + 8;
    const size_t gq_r  = (size_t)(b * LQS + q0 + row_r);
    const size_t gq_r8 = gq_r + 8;
    const int* gm_r  = gmask + gq_r  * LKS;
    const int* gm_r8 = gmask + gq_r8 * LKS;

    /* attn coalesced-store addressing: warp covers rows p*16 + h*8 + {i*2 + lane/16} */
    const int st_row  = p * 16 + h * 8 + (lane >> 4);   /* +2 per instruction */
    float* attn_st = out_attn + ((size_t)(b * LQS + q0 + st_row)) * LKS + (lane & 15) * 4;

    /* prologue: kv tile 0 */
    issue_kv(sb + OFF_KV, (size_t)(b * NTILE), tid);
    CP_COMMIT();

    /* stage Q (scaled 1/8), split hi/lo bf16, SW128 */
    {
        const float4* Qg4 = (const float4*)(Qg + ((size_t)(b * LQS + q0)) * DIMS);
        #pragma unroll
        for (int i = 0; i < 4; ++i) {
            int idx = tid + 256 * i;                 /* 1024 float4 */
            int row = idx >> 4, dp4 = idx & 15;
            float4 v = Qg4[idx];
            v.x *= 0.125f; v.y *= 0.125f; v.z *= 0.125f; v.w *= 0.125f;
            uint32_t h0, l0, h1, l1;
            split2(make_float2(v.x, v.y), h0, l0);
            split2(make_float2(v.z, v.w), h1, l1);
            uint32_t off = SWZ((uint32_t)(row * 128 + dp4 * 8));
            *(uint2*)(smem + OFF_Q   + off) = make_uint2(h0, h1);
            *(uint2*)(smem + OFF_QLO + off) = make_uint2(l0, l1);
        }
    }

    /* gmask prefetch tile 0 into registers */
    int2 gc[4], gc8[4];
    #pragma unroll
    for (int j = 0; j < 4; ++j) {
        const int c = h * 32 + j * 8 + 2 * qg;
        gc[j]  = __ldg((const int2*)(gm_r  + c));
        gc8[j] = __ldg((const int2*)(gm_r8 + c));
    }

    float oc[4][4];
    #pragma unroll
    for (int j = 0; j < 4; ++j)
        #pragma unroll
        for (int c = 0; c < 4; ++c) oc[j][c] = 0.f;
    float l0s = 0.f, l1s = 0.f;

    const uint32_t Pb = OFF_P + (uint32_t)(p * 2048);
    /* smem read base for the attn-store phase (this warp's rows of the pair tile) */
    const uint32_t Prd = Pb + (uint32_t)(h * 8 + (lane >> 4)) * 128u;

    #pragma unroll 1
    for (int kt = 0; kt < NTILE; ++kt) {
        const int kbase = kt * BKT;
        const uint32_t cb = OFF_KV + (uint32_t)((kt & 1) * KV_BYTES);

        __syncthreads();    /* prev PV done -> safe to overwrite other buffer */
        if (kt + 1 < NTILE)
            issue_kv(sb + OFF_KV + (uint32_t)(((kt + 1) & 1) * KV_BYTES),
                     (size_t)(b * NTILE + kt + 1), tid);
        CP_COMMIT();

        /* gmask prefetch for next tile (regular LDG, consumed next iter) */
        int2 gn[4], gn8[4];
        if (kt + 1 < NTILE) {
            const int nb = kbase + BKT;
            #pragma unroll
            for (int j = 0; j < 4; ++j) {
                const int c = nb + h * 32 + j * 8 + 2 * qg;
                gn[j]  = __ldg((const int2*)(gm_r  + c));
                gn8[j] = __ldg((const int2*)(gm_r8 + c));
            }
        }

        asm volatile("cp.async.wait_group 1;" ::: "memory");
        __syncthreads();    /* kv(kt) visible */

        /* ---- S = Q K^T for this warp's 32-key half (bf16 EC, 3-pass) ---- */
        float sc[4][4];
        #pragma unroll
        for (int j = 0; j < 4; ++j)
            #pragma unroll
            for (int c = 0; c < 4; ++c) sc[j][c] = 0.f;

        #pragma unroll
        for (int t = 0; t < 4; ++t) {
            uint32_t qh4[4], ql4[4];
            uint32_t offq = SWZ((uint32_t)((p * 16 + l16) * 128 + t * 32 + (lane >> 4) * 16));
            ldm_x4(qh4, sb + OFF_Q   + offq);
            ldm_x4(ql4, sb + OFF_QLO + offq);
            #pragma unroll
            for (int jp = 0; jp < 2; ++jp) {
                uint32_t kh4[4], kl4[4];
                int krow = h * 32 + jp * 16 + (lane & 7) + ((lane >> 4) << 3);
                uint32_t off = SWZ((uint32_t)(krow * 128 + t * 32 + ((lane >> 3) & 1) * 16));
                ldm_x4(kh4, sb + cb + off);          /* Khi */
                ldm_x4(kl4, sb + cb + 8192 + off);   /* Klo */
                mma_bf16(sc[2*jp],   qh4, kh4);
                mma_bf16(sc[2*jp],   ql4, kh4);
                mma_bf16(sc[2*jp],   qh4, kl4);
                mma_bf16(sc[2*jp+1], qh4, kh4 + 2);
                mma_bf16(sc[2*jp+1], ql4, kh4 + 2);
                mma_bf16(sc[2*jp+1], qh4, kl4 + 2);
            }
        }

        /* ---- epilogue: mask + exp + row sums + P(fp16) pack to smem ---- */
        #pragma unroll
        for (int j = 0; j < 4; ++j) {
            const int c = h * 32 + j * 8 + 2 * qg;
            const int gcol = kbase + c;
            int2 km = __ldg((const int2*)(kmb + gcol));
            float e0 = (km.x && gc[j].x)  ? __expf(sc[j][0]) : 0.f;
            float e1 = (km.y && gc[j].y)  ? __expf(sc[j][1]) : 0.f;
            float e2 = (km.x && gc8[j].x) ? __expf(sc[j][2]) : 0.f;
            float e3 = (km.y && gc8[j].y) ? __expf(sc[j][3]) : 0.f;
            l0s += e0 + e1; l1s += e2 + e3;
            uint32_t offr  = SWZ((uint32_t)(r  * 128 + c * 2));
            uint32_t offr8 = SWZ((uint32_t)((r + 8) * 128 + c * 2));
            *(uint32_t*)(smem + Pb + offr)  = pack2h(e0, e1);
            *(uint32_t*)(smem + Pb + offr8) = pack2h(e2, e3);
        }

        /* pair barrier: P tile complete (2 warps, 64 threads) */
        asm volatile("bar.sync %0, 64;" :: "r"(1 + p) : "memory");

        /* ---- coalesced attn store from P smem (fp16 -> fp32) ---- */
        #pragma unroll
        for (int i = 0; i < 4; ++i) {
            uint32_t a = Prd + (uint32_t)(i * 256);             /* +2 rows per i */
            uint2 w = *(const uint2*)(smem + SWZ(a + (lane & 15) * 8u)
                                      - (a & 0u) );             /* swizzle applied below */
            /* NOTE: swizzle must apply to full offset; recompute properly: */
            (void)w;
            uint32_t full = (uint32_t)((h * 8 + (lane >> 4) + i * 2) * 128 + (lane & 15) * 8);
            uint2 wv = *(const uint2*)(smem + Pb + SWZ(full));
            __half2 h01 = *(__half2*)&wv.x;
            __half2 h23 = *(__half2*)&wv.y;
            float2 f01 = __half22float2(h01);
            float2 f23 = __half22float2(h23);
            *(float4*)(attn_st + (size_t)(i * 2) * LKS + kbase) =
                make_float4(f01.x, f01.y, f23.x, f23.y);
        }

        /* ---- PV: O[16 x 32d-half] over all 64 keys (fp16: Ph*Vh + Ph*Vl) ---- */
        #pragma unroll
        for (int ks = 0; ks < 4; ++ks) {
            uint32_t pah4[4];
            uint32_t offp = SWZ((uint32_t)(l16 * 128 + ks * 32 + (lane >> 4) * 16));
            ldm_x4(pah4, sb + Pb + offp);
            #pragma unroll
            for (int j2p = 0; j2p < 2; ++j2p) {
                uint32_t vh4[4], vl4[4];
                uint32_t offv = SWZ((uint32_t)((ks * 16 + l16) * 128 +
                                               h * 64 + j2p * 32 + (lane >> 4) * 16));
                ldm_x4t(vh4, sb + cb + 16384 + offv);   /* Vhi */
                ldm_x4t(vl4, sb + cb + 24576 + offv);   /* Vlo */
                mma_f16(oc[2*j2p],   pah4, vh4);
                mma_f16(oc[2*j2p],   pah4, vl4);
                mma_f16(oc[2*j2p+1], pah4, vh4 + 2);
                mma_f16(oc[2*j2p+1], pah4, vl4 + 2);
            }
        }

        if (kt + 1 < NTILE) {
            #pragma unroll
            for (int j = 0; j < 4; ++j) { gc[j] = gn[j]; gc8[j] = gn8[j]; }
        }
    }

    /* ---- half row sums -> inv ---- */
    l0s += __shfl_xor_sync(0xffffffffu, l0s, 1);
    l0s += __shfl_xor_sync(0xffffffffu, l0s, 2);
    l1s += __shfl_xor_sync(0xffffffffu, l1s, 1);
    l1s += __shfl_xor_sync(0xffffffffu, l1s, 2);
    if (qg == 0) {
        sLH[h * 64 + row_r]  = l0s;
        sLH[h * 64 + row_r8] = l1s;
    }
    __syncthreads();
    if (tid < LQT) {
        float l = sLH[tid] + sLH[64 + tid];
        sInv[tid] = (qmask[(size_t)b * LQS + q0 + tid] != 0) ? (1.0f / l) : 0.0f;
    }
    __syncthreads();

    /* ---- store attn_value (own d-half) ---- */
    {
        const float inv0 = sInv[row_r];
        const float inv1 = sInv[row_r8];
        float* av_r  = out_av + gq_r  * DIMS;
        float* av_r8 = out_av + gq_r8 * DIMS;
        #pragma unroll
        for (int jj = 0; jj < 4; ++jj) {
            const int col = h * 32 + jj * 8 + 2 * qg;
            *(float2*)(av_r  + col) = make_float2(oc[jj][0] * inv0, oc[jj][1] * inv0);
            *(float2*)(av_r8 + col) = make_float2(oc[jj][2] * inv1, oc[jj][3] * inv1);
        }
    }

    /* ---- fused normalize of this CTA's attn rows ---- */
    __threadfence_block();
    __syncthreads();
    {
        float4* base = (float4*)(out_attn + ((size_t)(b * LQS + q0)) * LKS);
        for (int i = tid; i < LQT * 256; i += NTHREADS) {
            const float inv = sInv[i >> 8];
            float4 v = base[i];
            v.x *= inv; v.y *= inv; v.z *= inv; v.w *= inv;
            base[i] = v;
        }
    }
}

extern "C" void kernel_launch(void* const* d_in, const int* in_sizes, int n_in,
                              void* d_out, int out_size) {
    const float* Q  = (const float*)d_in[0];
    const float* K  = (const float*)d_in[1];
    const float* V  = (const float*)d_in[2];
    const int*   qm = (const int*)d_in[3];
    const int*   km = (const int*)d_in[4];
    const int*   mk = (const int*)d_in[5];

    const long long NAV = (long long)BATCH * LQS * DIMS;
    float* out  = (float*)d_out;
    float* av   = out;
    float* attn = out + NAV;
    (void)out_size; (void)in_sizes; (void)n_in;

    conv_kv_kernel<<<BATCH * NTILE, 256>>>(K, V);

    cudaFuncSetAttribute(attn_mma_kernel, cudaFuncAttributeMaxDynamicSharedMemorySize,
                         SMEM_BYTES);
    dim3 grid(LQS / LQT, BATCH);
    attn_mma_kernel<<<grid, NTHREADS, SMEM_BYTES>>>(Q, qm, km, mk, av, attn);
}

// round 15
// speedup vs baseline: 1.4475x; 1.1157x over previous
#include <cuda_runtime.h>
#include <cuda_bf16.h>
#include <cuda_fp16.h>
#include <cstdint>

#define BATCH 64
#define LQS   1024
#define LKS   1024
#define DIMS  64
#define NTHREADS 256
#define LQT   64        /* q-rows per CTA (4 pairs x 16) */
#define BKT   64        /* keys per tile */
#define NTILE 16

/* ---- shared memory byte offsets ---- */
#define OFF_SLH  0                      /* 2 x 64 floats: half row sums */
#define OFF_SINV 512                    /* 64 floats: inv */
#define OFF_Q    1024                   /* Qhi 8K */
#define OFF_QLO  (OFF_Q + 8192)         /* Qlo 8K */
#define OFF_KV   17408                  /* ring: 2 x 24K (Khi,Klo,Vhi 8K each) */
#define KV_BYTES 24576
#define OFF_P    (OFF_KV + 2 * KV_BYTES)    /* 66560: 4 pairs x 2K (fp16 P) */
#define SMEM_BYTES (OFF_P + 8192)           /* 74752 */

#define SWZ(x) ((x) ^ (((x) >> 3) & 0x70))

/* ---- global scratch: pre-swizzled K (bf16 hi/lo) and V (fp16 hi) tiles ---- */
__device__ uint4 g_Khi[BATCH * NTILE * 512];
__device__ uint4 g_Klo[BATCH * NTILE * 512];
__device__ uint4 g_Vhi[BATCH * NTILE * 512];

/* ------------------------- helpers ------------------------- */
__device__ __forceinline__ uint32_t smem_u32(const void* p) {
    uint32_t a;
    asm("{ .reg .u64 t; cvta.to.shared.u64 t, %1; cvt.u32.u64 %0, t; }" : "=r"(a) : "l"(p));
    return a;
}
__device__ __forceinline__ void cp16(uint32_t d, const void* s) {
    asm volatile("cp.async.cg.shared.global [%0], [%1], 16;" :: "r"(d), "l"(s) : "memory");
}
#define CP_COMMIT() asm volatile("cp.async.commit_group;" ::: "memory")
__device__ __forceinline__ void ldm_x4(uint32_t* d, uint32_t a) {
    asm volatile("ldmatrix.sync.aligned.m8n8.x4.shared.b16 {%0,%1,%2,%3}, [%4];"
        : "=r"(d[0]), "=r"(d[1]), "=r"(d[2]), "=r"(d[3]) : "r"(a));
}
__device__ __forceinline__ void ldm_x4t(uint32_t* d, uint32_t a) {
    asm volatile("ldmatrix.sync.aligned.m8n8.x4.trans.shared.b16 {%0,%1,%2,%3}, [%4];"
        : "=r"(d[0]), "=r"(d[1]), "=r"(d[2]), "=r"(d[3]) : "r"(a));
}
__device__ __forceinline__ void mma_bf16(float* c, const uint32_t* a, const uint32_t* b) {
    asm volatile("mma.sync.aligned.m16n8k16.row.col.f32.bf16.bf16.f32 "
        "{%0,%1,%2,%3}, {%4,%5,%6,%7}, {%8,%9}, {%0,%1,%2,%3};"
        : "+f"(c[0]), "+f"(c[1]), "+f"(c[2]), "+f"(c[3])
        : "r"(a[0]), "r"(a[1]), "r"(a[2]), "r"(a[3]), "r"(b[0]), "r"(b[1]));
}
__device__ __forceinline__ void mma_f16(float* c, const uint32_t* a, const uint32_t* b) {
    asm volatile("mma.sync.aligned.m16n8k16.row.col.f32.f16.f16.f32 "
        "{%0,%1,%2,%3}, {%4,%5,%6,%7}, {%8,%9}, {%0,%1,%2,%3};"
        : "+f"(c[0]), "+f"(c[1]), "+f"(c[2]), "+f"(c[3])
        : "r"(a[0]), "r"(a[1]), "r"(a[2]), "r"(a[3]), "r"(b[0]), "r"(b[1]));
}
__device__ __forceinline__ uint32_t pack2bf(float a, float b) {
    __nv_bfloat16 ha = __float2bfloat16(a), hb = __float2bfloat16(b);
    return (uint32_t)__bfloat16_as_ushort(ha) | ((uint32_t)__bfloat16_as_ushort(hb) << 16);
}
__device__ __forceinline__ void split2(float2 v, uint32_t& hw, uint32_t& lw) {
    __nv_bfloat16 h0 = __float2bfloat16(v.x), h1 = __float2bfloat16(v.y);
    hw = (uint32_t)__bfloat16_as_ushort(h0) | ((uint32_t)__bfloat16_as_ushort(h1) << 16);
    lw = pack2bf(v.x - __bfloat162float(h0), v.y - __bfloat162float(h1));
}
__device__ __forceinline__ uint32_t pack2h(float a, float b) {
    __half ha = __float2half_rn(a), hb = __float2half_rn(b);
    return (uint32_t)__half_as_ushort(ha) | ((uint32_t)__half_as_ushort(hb) << 16);
}

/* ---- prologue kernel: K -> bf16 hi/lo, V -> fp16 hi, swizzled (coalesced) ---- */
__global__ __launch_bounds__(256)
void conv_kv_kernel(const float* __restrict__ Kg, const float* __restrict__ Vg)
{
    const int tile = blockIdx.x;            /* 0..1023 = b*16+kt */
    const size_t tb = (size_t)tile * 8192;
    const size_t srow0 = (size_t)tile * 64; /* first key row of tile */
    #pragma unroll
    for (int it = 0; it < 4; ++it) {
        int item = threadIdx.x + 256 * it;  /* 0..1023 */
        int arr = item >> 9;                /* 0:K 1:V */
        int row = (item >> 3) & 63;
        int dg  = item & 7;
        const float4* src = (const float4*)((arr ? Vg : Kg) + (srow0 + row) * DIMS + dg * 8);
        float4 a = src[0], c = src[1];
        uint32_t off = SWZ((uint32_t)(row * 128 + dg * 16));
        if (arr) {
            *(uint4*)((char*)g_Vhi + tb + off) =
                make_uint4(pack2h(a.x, a.y), pack2h(a.z, a.w),
                           pack2h(c.x, c.y), pack2h(c.z, c.w));
        } else {
            uint32_t h0, l0, h1, l1, h2, l2, h3, l3;
            split2(make_float2(a.x, a.y), h0, l0);
            split2(make_float2(a.z, a.w), h1, l1);
            split2(make_float2(c.x, c.y), h2, l2);
            split2(make_float2(c.z, c.w), h3, l3);
            *(uint4*)((char*)g_Khi + tb + off) = make_uint4(h0, h1, h2, h3);
            *(uint4*)((char*)g_Klo + tb + off) = make_uint4(l0, l1, l2, l3);
        }
    }
}

/* issue cp.asyncs for one KV tile (6 x 16B per thread) */
__device__ __forceinline__ void issue_kv(uint32_t dst, size_t tile, int tid) {
    const char* skhi = (const char*)g_Khi + tile * 8192;
    const char* sklo = (const char*)g_Klo + tile * 8192;
    const char* svhi = (const char*)g_Vhi + tile * 8192;
    #pragma unroll
    for (int ii = 0; ii < 2; ++ii) {
        int i = (tid + 256 * ii) * 16;
        cp16(dst + i,         skhi + i);
        cp16(dst + 8192 + i,  sklo + i);
        cp16(dst + 16384 + i, svhi + i);
    }
}

/* ============================ main kernel ============================ */
__global__ __launch_bounds__(NTHREADS, 2)
void attn_mma_kernel(const float* __restrict__ Qg,
                     const int* __restrict__ qmask, const int* __restrict__ kmask,
                     const int* __restrict__ gmask,
                     float* __restrict__ out_av, float* __restrict__ out_attn)
{
    extern __shared__ char smem[];
    const uint32_t sb = smem_u32(smem);
    float* sLH  = (float*)(smem + OFF_SLH);
    float* sInv = (float*)(smem + OFF_SINV);

    const int tid  = threadIdx.x;
    const int warp = tid >> 5;
    const int lane = tid & 31;
    const int l16  = lane & 15;
    const int qg   = lane & 3;
    const int r    = lane >> 2;
    const int p    = warp >> 1;     /* pair 0..3 */
    const int h    = warp & 1;      /* key-half / d-half */
    const int b    = blockIdx.y;
    const int q0   = blockIdx.x * LQT;

    const int* kmb = kmask + (size_t)b * LKS;
    const int row_r  = p * 16 + r;
    const int row_r8 = row_r + 8;
    const size_t gq_r  = (size_t)(b * LQS + q0 + row_r);
    const size_t gq_r8 = gq_r + 8;
    const int* gm_r  = gmask + gq_r  * LKS;
    const int* gm_r8 = gmask + gq_r8 * LKS;

    /* attn coalesced-store addressing */
    const int st_row  = p * 16 + h * 8 + (lane >> 4);   /* +2 per instruction */
    float* attn_st = out_attn + ((size_t)(b * LQS + q0 + st_row)) * LKS + (lane & 15) * 4;

    /* prologue: kv tile 0 */
    issue_kv(sb + OFF_KV, (size_t)(b * NTILE), tid);
    CP_COMMIT();

    /* stage Q (scaled 1/8), split hi/lo bf16, SW128 */
    {
        const float4* Qg4 = (const float4*)(Qg + ((size_t)(b * LQS + q0)) * DIMS);
        #pragma unroll
        for (int i = 0; i < 4; ++i) {
            int idx = tid + 256 * i;                 /* 1024 float4 */
            int row = idx >> 4, dp4 = idx & 15;
            float4 v = Qg4[idx];
            v.x *= 0.125f; v.y *= 0.125f; v.z *= 0.125f; v.w *= 0.125f;
            uint32_t h0, l0, h1, l1;
            split2(make_float2(v.x, v.y), h0, l0);
            split2(make_float2(v.z, v.w), h1, l1);
            uint32_t off = SWZ((uint32_t)(row * 128 + dp4 * 8));
            *(uint2*)(smem + OFF_Q   + off) = make_uint2(h0, h1);
            *(uint2*)(smem + OFF_QLO + off) = make_uint2(l0, l1);
        }
    }

    /* gmask prefetch tile 0 into registers */
    int2 gc[4], gc8[4];
    #pragma unroll
    for (int j = 0; j < 4; ++j) {
        const int c = h * 32 + j * 8 + 2 * qg;
        gc[j]  = __ldg((const int2*)(gm_r  + c));
        gc8[j] = __ldg((const int2*)(gm_r8 + c));
    }

    float oc[4][4];
    #pragma unroll
    for (int j = 0; j < 4; ++j)
        #pragma unroll
        for (int c = 0; c < 4; ++c) oc[j][c] = 0.f;
    float l0s = 0.f, l1s = 0.f;

    const uint32_t Pb = OFF_P + (uint32_t)(p * 2048);

    #pragma unroll 1
    for (int kt = 0; kt < NTILE; ++kt) {
        const int kbase = kt * BKT;
        const uint32_t cb = OFF_KV + (uint32_t)((kt & 1) * KV_BYTES);

        __syncthreads();    /* prev PV done -> safe to overwrite other buffer */
        if (kt + 1 < NTILE)
            issue_kv(sb + OFF_KV + (uint32_t)(((kt + 1) & 1) * KV_BYTES),
                     (size_t)(b * NTILE + kt + 1), tid);
        CP_COMMIT();

        /* gmask prefetch for next tile (regular LDG, consumed next iter) */
        int2 gn[4], gn8[4];
        if (kt + 1 < NTILE) {
            const int nb = kbase + BKT;
            #pragma unroll
            for (int j = 0; j < 4; ++j) {
                const int c = nb + h * 32 + j * 8 + 2 * qg;
                gn[j]  = __ldg((const int2*)(gm_r  + c));
                gn8[j] = __ldg((const int2*)(gm_r8 + c));
            }
        }

        asm volatile("cp.async.wait_group 1;" ::: "memory");
        __syncthreads();    /* kv(kt) visible */

        /* ---- S = Q K^T for this warp's 32-key half (bf16 EC, 3-pass) ---- */
        float sc[4][4];
        #pragma unroll
        for (int j = 0; j < 4; ++j)
            #pragma unroll
            for (int c = 0; c < 4; ++c) sc[j][c] = 0.f;

        #pragma unroll
        for (int t = 0; t < 4; ++t) {
            uint32_t qh4[4], ql4[4];
            uint32_t offq = SWZ((uint32_t)((p * 16 + l16) * 128 + t * 32 + (lane >> 4) * 16));
            ldm_x4(qh4, sb + OFF_Q   + offq);
            ldm_x4(ql4, sb + OFF_QLO + offq);
            #pragma unroll
            for (int jp = 0; jp < 2; ++jp) {
                uint32_t kh4[4], kl4[4];
                int krow = h * 32 + jp * 16 + (lane & 7) + ((lane >> 4) << 3);
                uint32_t off = SWZ((uint32_t)(krow * 128 + t * 32 + ((lane >> 3) & 1) * 16));
                ldm_x4(kh4, sb + cb + off);          /* Khi */
                ldm_x4(kl4, sb + cb + 8192 + off);   /* Klo */
                mma_bf16(sc[2*jp],   qh4, kh4);
                mma_bf16(sc[2*jp],   ql4, kh4);
                mma_bf16(sc[2*jp],   qh4, kl4);
                mma_bf16(sc[2*jp+1], qh4, kh4 + 2);
                mma_bf16(sc[2*jp+1], ql4, kh4 + 2);
                mma_bf16(sc[2*jp+1], qh4, kl4 + 2);
            }
        }

        /* ---- epilogue: mask + exp + row sums + P(fp16) pack to smem ---- */
        #pragma unroll
        for (int j = 0; j < 4; ++j) {
            const int c = h * 32 + j * 8 + 2 * qg;
            const int gcol = kbase + c;
            int2 km = __ldg((const int2*)(kmb + gcol));
            float e0 = (km.x && gc[j].x)  ? __expf(sc[j][0]) : 0.f;
            float e1 = (km.y && gc[j].y)  ? __expf(sc[j][1]) : 0.f;
            float e2 = (km.x && gc8[j].x) ? __expf(sc[j][2]) : 0.f;
            float e3 = (km.y && gc8[j].y) ? __expf(sc[j][3]) : 0.f;
            l0s += e0 + e1; l1s += e2 + e3;
            uint32_t offr  = SWZ((uint32_t)(r  * 128 + c * 2));
            uint32_t offr8 = SWZ((uint32_t)((r + 8) * 128 + c * 2));
            *(uint32_t*)(smem + Pb + offr)  = pack2h(e0, e1);
            *(uint32_t*)(smem + Pb + offr8) = pack2h(e2, e3);
        }

        /* pair barrier: P tile complete (2 warps, 64 threads) */
        asm volatile("bar.sync %0, 64;" :: "r"(1 + p) : "memory");

        /* ---- PV: O[16 x 32d-half] over all 64 keys (fp16: Ph*Vhi) ---- */
        #pragma unroll
        for (int ks = 0; ks < 4; ++ks) {
            uint32_t pah4[4];
            uint32_t offp = SWZ((uint32_t)(l16 * 128 + ks * 32 + (lane >> 4) * 16));
            ldm_x4(pah4, sb + Pb + offp);
            #pragma unroll
            for (int j2p = 0; j2p < 2; ++j2p) {
                uint32_t vh4[4];
                uint32_t offv = SWZ((uint32_t)((ks * 16 + l16) * 128 +
                                               h * 64 + j2p * 32 + (lane >> 4) * 16));
                ldm_x4t(vh4, sb + cb + 16384 + offv);   /* Vhi */
                mma_f16(oc[2*j2p],   pah4, vh4);
                mma_f16(oc[2*j2p+1], pah4, vh4 + 2);
            }
        }

        /* ---- coalesced attn store from P smem (fp16 -> fp32), after MMAs ---- */
        #pragma unroll
        for (int i = 0; i < 4; ++i) {
            uint32_t full = (uint32_t)((h * 8 + (lane >> 4) + i * 2) * 128 + (lane & 15) * 8);
            uint2 wv = *(const uint2*)(smem + Pb + SWZ(full));
            __half2 h01 = *(__half2*)&wv.x;
            __half2 h23 = *(__half2*)&wv.y;
            float2 f01 = __half22float2(h01);
            float2 f23 = __half22float2(h23);
            *(float4*)(attn_st + (size_t)(i * 2) * LKS + kbase) =
                make_float4(f01.x, f01.y, f23.x, f23.y);
        }

        if (kt + 1 < NTILE) {
            #pragma unroll
            for (int j = 0; j < 4; ++j) { gc[j] = gn[j]; gc8[j] = gn8[j]; }
        }
    }

    /* ---- half row sums -> inv ---- */
    l0s += __shfl_xor_sync(0xffffffffu, l0s, 1);
    l0s += __shfl_xor_sync(0xffffffffu, l0s, 2);
    l1s += __shfl_xor_sync(0xffffffffu, l1s, 1);
    l1s += __shfl_xor_sync(0xffffffffu, l1s, 2);
    if (qg == 0) {
        sLH[h * 64 + row_r]  = l0s;
        sLH[h * 64 + row_r8] = l1s;
    }
    __syncthreads();
    if (tid < LQT) {
        float l = sLH[tid] + sLH[64 + tid];
        sInv[tid] = (qmask[(size_t)b * LQS + q0 + tid] != 0) ? (1.0f / l) : 0.0f;
    }
    __syncthreads();

    /* ---- store attn_value (own d-half) ---- */
    {
        const float inv0 = sInv[row_r];
        const float inv1 = sInv[row_r8];
        float* av_r  = out_av + gq_r  * DIMS;
        float* av_r8 = out_av + gq_r8 * DIMS;
        #pragma unroll
        for (int jj = 0; jj < 4; ++jj) {
            const int col = h * 32 + jj * 8 + 2 * qg;
            *(float2*)(av_r  + col) = make_float2(oc[jj][0] * inv0, oc[jj][1] * inv0);
            *(float2*)(av_r8 + col) = make_float2(oc[jj][2] * inv1, oc[jj][3] * inv1);
        }
    }

    /* ---- fused normalize of this CTA's attn rows ---- */
    __threadfence_block();
    __syncthreads();
    {
        float4* base = (float4*)(out_attn + ((size_t)(b * LQS + q0)) * LKS);
        for (int i = tid; i < LQT * 256; i += NTHREADS) {
            const float inv = sInv[i >> 8];
            float4 v = base[i];
            v.x *= inv; v.y *= inv; v.z *= inv; v.w *= inv;
            base[i] = v;
        }
    }
}

extern "C" void kernel_launch(void* const* d_in, const int* in_sizes, int n_in,
                              void* d_out, int out_size) {
    const float* Q  = (const float*)d_in[0];
    const float* K  = (const float*)d_in[1];
    const float* V  = (const float*)d_in[2];
    const int*   qm = (const int*)d_in[3];
    const int*   km = (const int*)d_in[4];
    const int*   mk = (const int*)d_in[5];

    const long long NAV = (long long)BATCH * LQS * DIMS;
    float* out  = (float*)d_out;
    float* av   = out;
    float* attn = out + NAV;
    (void)out_size; (void)in_sizes; (void)n_in;

    conv_kv_kernel<<<BATCH * NTILE, 256>>>(K, V);

    cudaFuncSetAttribute(attn_mma_kernel, cudaFuncAttributeMaxDynamicSharedMemorySize,
                         SMEM_BYTES);
    dim3 grid(LQS / LQT, BATCH);
    attn_mma_kernel<<<grid, NTHREADS, SMEM_BYTES>>>(Q, qm, km, mk, av, attn);
}